// round 1
// baseline (speedup 1.0000x reference)
#include <cuda_runtime.h>
#include <math.h>

// Shapes (fixed by the problem; V derived from in_sizes at launch)
#define H 1024
#define E 1024
#define L 2048
#define HE 2048          // H + E
#define H3 3072          // 3*H
#define ECHUNKS 8        // split of E for the scores GEMV
#define ECHUNK  (E / ECHUNKS)

// ---------------- scratch (__device__ globals; no allocation) ----------------
__device__ __align__(16) float g_d[E];        // d vector
__device__ __align__(16) float g_x[HE];       // concat(g, c)
__device__ __align__(16) float g_part[ECHUNKS * L]; // partial scores
__device__ __align__(16) float g_attn[L];     // softmax weights
__device__ __align__(16) float g_gx[H3];
__device__ __align__(16) float g_gh[H3];
__device__ __align__(16) float g_hnew[H];
__device__ float g_lse;

// ---------------- helpers ----------------
__device__ __forceinline__ float warp_sum(float v) {
    #pragma unroll
    for (int o = 16; o; o >>= 1) v += __shfl_down_sync(0xffffffffu, v, o);
    return v;
}
__device__ __forceinline__ float warp_max(float v) {
    #pragma unroll
    for (int o = 16; o; o >>= 1) v = fmaxf(v, __shfl_down_sync(0xffffffffu, v, o));
    return v;
}
__device__ __forceinline__ float dot4(const float4 a, const float4 b) {
    return a.x * b.x + a.y * b.y + a.z * b.z + a.w * b.w;
}
// warp-cooperative dot of two contiguous float arrays of length n (n % 4 == 0)
__device__ __forceinline__ float warp_dot(const float* __restrict__ a,
                                          const float* __restrict__ b,
                                          int n, int lane) {
    const float4* a4 = reinterpret_cast<const float4*>(a);
    const float4* b4 = reinterpret_cast<const float4*>(b);
    int n4 = n >> 2;
    float acc = 0.f;
    #pragma unroll 4
    for (int i = lane; i < n4; i += 32) acc += dot4(a4[i], b4[i]);
    return warp_sum(acc);
}
__device__ __forceinline__ float sigmoidf(float x) { return 1.0f / (1.0f + expf(-x)); }

// ---------------- k1: d[e] = W_t[e,:]·h + b_t[e] + emb[y,e]; x[0:H] = g ----------------
__global__ void k1_dvec(const int* __restrict__ y, const float* __restrict__ h,
                        const float* __restrict__ emb, const float* __restrict__ W_t,
                        const float* __restrict__ b_t) {
    int e    = (blockIdx.x * blockDim.x + threadIdx.x) >> 5;
    int lane = threadIdx.x & 31;
    if (e >= E) return;
    float acc = warp_dot(W_t + (size_t)e * H, h, H, lane);
    if (lane == 0) {
        float g = emb[(size_t)y[0] * H + e];
        g_d[e] = acc + b_t[e] + g;
        g_x[e] = g;
    }
}

// ---------------- k2: partial scores over E-chunks (coalesced over l) ----------------
__global__ void k2_scores(const float* __restrict__ cnn_a) {
    __shared__ float ds[ECHUNK];
    int l  = blockIdx.x * blockDim.x + threadIdx.x;   // 0..L-1 (gridDim.x * 256 == L)
    int e0 = blockIdx.y * ECHUNK;
    for (int i = threadIdx.x; i < ECHUNK; i += blockDim.x) ds[i] = g_d[e0 + i];
    __syncthreads();
    const float* __restrict__ col = cnn_a + (size_t)e0 * L + l;
    float acc = 0.f;
    #pragma unroll 8
    for (int e = 0; e < ECHUNK; e++) acc += ds[e] * col[(size_t)e * L];
    g_part[blockIdx.y * L + l] = acc;
}

// ---------------- k3: softmax over L (single block, 1024 threads) ----------------
__global__ void k3_softmax() {
    __shared__ float red[32];
    __shared__ float bval;
    int t = threadIdx.x;
    float s0 = 0.f, s1 = 0.f;
    #pragma unroll
    for (int p = 0; p < ECHUNKS; p++) {
        s0 += g_part[p * L + t];
        s1 += g_part[p * L + t + 1024];
    }
    // block max
    float m = warp_max(fmaxf(s0, s1));
    if ((t & 31) == 0) red[t >> 5] = m;
    __syncthreads();
    if (t < 32) { float v = red[t]; v = warp_max(v); if (t == 0) bval = v; }
    __syncthreads();
    float M = bval;
    float e0 = expf(s0 - M), e1 = expf(s1 - M);
    float s = warp_sum(e0 + e1);
    __syncthreads();
    if ((t & 31) == 0) red[t >> 5] = s;
    __syncthreads();
    if (t < 32) { float v = red[t]; v = warp_sum(v); if (t == 0) bval = v; }
    __syncthreads();
    float inv = 1.0f / bval;
    g_attn[t]        = e0 * inv;
    g_attn[t + 1024] = e1 * inv;
}

// ---------------- k4: c[h] = attn · cnn_c[h,:]; x[H + h] = c[h] ----------------
__global__ void k4_context(const float* __restrict__ cnn_c) {
    int r    = (blockIdx.x * blockDim.x + threadIdx.x) >> 5;
    int lane = threadIdx.x & 31;
    if (r >= H) return;
    float acc = warp_dot(cnn_c + (size_t)r * L, g_attn, L, lane);
    if (lane == 0) g_x[H + r] = acc;
}

// ---------------- k5: gx = W_ih·x + b_ih ; gh = W_hh·h + b_hh ----------------
__global__ void k5_gru_mats(const float* __restrict__ W_ih, const float* __restrict__ W_hh,
                            const float* __restrict__ b_ih, const float* __restrict__ b_hh,
                            const float* __restrict__ h) {
    int r    = (blockIdx.x * blockDim.x + threadIdx.x) >> 5;
    int lane = threadIdx.x & 31;
    if (r < H3) {
        float acc = warp_dot(W_ih + (size_t)r * HE, g_x, HE, lane);
        if (lane == 0) g_gx[r] = acc + b_ih[r];
    } else if (r < 2 * H3) {
        int j = r - H3;
        float acc = warp_dot(W_hh + (size_t)j * H, h, H, lane);
        if (lane == 0) g_gh[j] = acc + b_hh[j];
    }
}

// ---------------- k6: gate combine -> h_new (also written to d_out tail) ----------------
__global__ void k6_combine(const float* __restrict__ h, float* __restrict__ out_hidden) {
    int i = threadIdx.x;
    float r  = sigmoidf(g_gx[i]          + g_gh[i]);
    float z  = sigmoidf(g_gx[H + i]      + g_gh[H + i]);
    float n  = tanhf   (g_gx[2 * H + i]  + r * g_gh[2 * H + i]);
    float hn = (1.0f - z) * n + z * h[i];
    g_hnew[i] = hn;
    out_hidden[i] = hn;
}

// ---------------- k7: logits[v] = h_new · W_o[v,:] + b_o[v]  (dominant, 206 MB) -------
__global__ void k7_logits(const float* __restrict__ W_o, const float* __restrict__ b_o,
                          float* __restrict__ logits, int V) {
    int v    = (blockIdx.x * blockDim.x + threadIdx.x) >> 5;
    int lane = threadIdx.x & 31;
    if (v >= V) return;
    float acc = warp_dot(W_o + (size_t)v * H, g_hnew, H, lane);
    if (lane == 0) logits[v] = acc + b_o[v];
}

// ---------------- k8: logsumexp over V (single block) ----------------
__global__ void k8_lse(const float* __restrict__ logits, int V) {
    __shared__ float red[32];
    __shared__ float bval;
    int t = threadIdx.x;
    float m = -INFINITY;
    for (int v = t; v < V; v += 1024) m = fmaxf(m, logits[v]);
    m = warp_max(m);
    if ((t & 31) == 0) red[t >> 5] = m;
    __syncthreads();
    if (t < 32) { float v = red[t]; v = warp_max(v); if (t == 0) bval = v; }
    __syncthreads();
    float M = bval;
    float s = 0.f;
    for (int v = t; v < V; v += 1024) s += expf(logits[v] - M);
    s = warp_sum(s);
    __syncthreads();
    if ((t & 31) == 0) red[t >> 5] = s;
    __syncthreads();
    if (t < 32) { float v = red[t]; v = warp_sum(v); if (t == 0) g_lse = M + logf(v); }
}

// ---------------- k9: out[v] = logits[v] - lse (in place) ----------------
__global__ void k9_norm(float* __restrict__ logits, int V) {
    int v = blockIdx.x * blockDim.x + threadIdx.x;
    if (v < V) logits[v] -= g_lse;
}

// ---------------- launch ----------------
extern "C" void kernel_launch(void* const* d_in, const int* in_sizes, int n_in,
                              void* d_out, int out_size) {
    const int*   y_i   = (const int*)  d_in[0];
    const float* h_i   = (const float*)d_in[1];
    const float* cnn_a = (const float*)d_in[2];
    const float* cnn_c = (const float*)d_in[3];
    const float* emb   = (const float*)d_in[4];
    const float* W_t   = (const float*)d_in[5];
    const float* b_t   = (const float*)d_in[6];
    const float* W_ih  = (const float*)d_in[7];
    const float* W_hh  = (const float*)d_in[8];
    const float* b_ih  = (const float*)d_in[9];
    const float* b_hh  = (const float*)d_in[10];
    const float* W_o   = (const float*)d_in[11];
    const float* b_o   = (const float*)d_in[12];

    const int V = in_sizes[11] / H;          // 50257
    float* out        = (float*)d_out;
    float* out_logits = out;                 // first V floats: log_softmax
    float* out_hidden = out + (out_size - H);// last H floats: gru_hidden

    // k1: 1024 rows, 8 warps/block
    k1_dvec<<<E / 8, 256>>>(y_i, h_i, emb, W_t, b_t);
    // k2: grid (L/256 col-tiles, ECHUNKS e-chunks)
    dim3 g2(L / 256, ECHUNKS);
    k2_scores<<<g2, 256>>>(cnn_a);
    // k3: softmax, one block
    k3_softmax<<<1, 1024>>>();
    // k4: context, 1024 rows
    k4_context<<<H / 8, 256>>>(cnn_c);
    // k5: 6144 warp-rows
    k5_gru_mats<<<(2 * H3) / 8, 256>>>(W_ih, W_hh, b_ih, b_hh, h_i);
    // k6: combine
    k6_combine<<<1, H>>>(h_i, out_hidden);
    // k7: logits, warp per row
    k7_logits<<<(V + 7) / 8, 256>>>(W_o, b_o, out_logits, V);
    // k8: logsumexp
    k8_lse<<<1, 1024>>>(out_logits, V);
    // k9: normalize in place
    k9_norm<<<(V + 255) / 256, 256>>>(out_logits, V);
}

// round 2
// speedup vs baseline: 1.1176x; 1.1176x over previous
#include <cuda_runtime.h>
#include <math.h>

// Shapes (fixed by the problem; V derived from in_sizes at launch)
#define H 1024
#define E 1024
#define L 2048
#define HE 2048          // H + E
#define H3 3072          // 3*H
#define ECHUNKS 16       // split of E for the scores GEMV
#define ECHUNK  (E / ECHUNKS)   // 64

// ---------------- scratch (__device__ globals; no allocation) ----------------
__device__ __align__(16) float g_d[E];               // d vector
__device__ __align__(16) float g_x[HE];              // concat(g, c)
__device__ __align__(16) float g_part[ECHUNKS * L];  // partial scores
__device__ __align__(16) float g_attn[L];            // softmax weights
__device__ __align__(16) float g_gx[H3];
__device__ __align__(16) float g_gh[H3];
__device__ __align__(16) float g_hnew[H];
__device__ float g_lse;

// ---------------- helpers ----------------
__device__ __forceinline__ float warp_sum(float v) {
    #pragma unroll
    for (int o = 16; o; o >>= 1) v += __shfl_down_sync(0xffffffffu, v, o);
    return v;
}
__device__ __forceinline__ float warp_max(float v) {
    #pragma unroll
    for (int o = 16; o; o >>= 1) v = fmaxf(v, __shfl_down_sync(0xffffffffu, v, o));
    return v;
}
__device__ __forceinline__ float dot4(const float4 a, const float4 b) {
    return a.x * b.x + a.y * b.y + a.z * b.z + a.w * b.w;
}
// block-wide sum; valid in thread 0. sred must hold >= blockDim/32 floats.
__device__ __forceinline__ float block_sum(float v, float* sred) {
    int lane = threadIdx.x & 31, w = threadIdx.x >> 5;
    v = warp_sum(v);
    if (lane == 0) sred[w] = v;
    __syncthreads();
    float r = 0.f;
    if (w == 0) {
        int nw = blockDim.x >> 5;
        r = (threadIdx.x < nw) ? sred[threadIdx.x] : 0.f;
        r = warp_sum(r);
    }
    return r;
}
__device__ __forceinline__ float sigmoidf(float x) { return 1.0f / (1.0f + expf(-x)); }

// ======== k1: block-per-row. d[e] = W_t[e,:]·h + b_t[e] + emb[y,e]; x[e] = g ========
__global__ __launch_bounds__(256) void k1_dvec(
        const int* __restrict__ y, const float* __restrict__ h,
        const float* __restrict__ emb, const float* __restrict__ W_t,
        const float* __restrict__ b_t) {
    __shared__ float sred[8];
    int e = blockIdx.x;              // 0..E-1
    int t = threadIdx.x;             // 0..255, one float4 each (row = 256 float4)
    const float4* w4 = reinterpret_cast<const float4*>(W_t + (size_t)e * H);
    const float4* h4 = reinterpret_cast<const float4*>(h);
    float acc = dot4(w4[t], h4[t]);
    acc = block_sum(acc, sred);
    if (t == 0) {
        float g = emb[(size_t)y[0] * H + e];
        g_d[e] = acc + b_t[e] + g;
        g_x[e] = g;
    }
}

// ======== k2: partial scores over E-chunks (coalesced over l) ========
__global__ __launch_bounds__(256) void k2_scores(const float* __restrict__ cnn_a) {
    __shared__ float ds[ECHUNK];
    int l  = blockIdx.x * blockDim.x + threadIdx.x;   // 0..L-1
    int e0 = blockIdx.y * ECHUNK;
    if (threadIdx.x < ECHUNK) ds[threadIdx.x] = g_d[e0 + threadIdx.x];
    __syncthreads();
    const float* __restrict__ col = cnn_a + (size_t)e0 * L + l;
    float a0 = 0.f, a1 = 0.f;
    #pragma unroll
    for (int e = 0; e < ECHUNK; e += 2) {
        a0 += ds[e]     * col[(size_t)e * L];
        a1 += ds[e + 1] * col[(size_t)(e + 1) * L];
    }
    g_part[blockIdx.y * L + l] = a0 + a1;
}

// ======== k3: softmax over L (single block, 1024 threads) ========
__global__ __launch_bounds__(1024) void k3_softmax() {
    __shared__ float red[32];
    __shared__ float bval;
    int t = threadIdx.x;
    float s0 = 0.f, s1 = 0.f;
    #pragma unroll
    for (int p = 0; p < ECHUNKS; p++) {
        s0 += g_part[p * L + t];
        s1 += g_part[p * L + t + 1024];
    }
    float m = warp_max(fmaxf(s0, s1));
    if ((t & 31) == 0) red[t >> 5] = m;
    __syncthreads();
    if (t < 32) { float v = red[t]; v = warp_max(v); if (t == 0) bval = v; }
    __syncthreads();
    float M = bval;
    float e0 = expf(s0 - M), e1 = expf(s1 - M);
    float s = warp_sum(e0 + e1);
    __syncthreads();
    if ((t & 31) == 0) red[t >> 5] = s;
    __syncthreads();
    if (t < 32) { float v = red[t]; v = warp_sum(v); if (t == 0) bval = v; }
    __syncthreads();
    float inv = 1.0f / bval;
    g_attn[t]        = e0 * inv;
    g_attn[t + 1024] = e1 * inv;
}

// ======== k4: block-per-row. c[r] = attn · cnn_c[r,:]; x[H+r] = c[r] ========
__global__ __launch_bounds__(256) void k4_context(const float* __restrict__ cnn_c) {
    __shared__ float sred[8];
    int r = blockIdx.x;              // 0..H-1
    int t = threadIdx.x;             // row = 512 float4 -> 2 per thread
    const float4* c4 = reinterpret_cast<const float4*>(cnn_c + (size_t)r * L);
    const float4* a4 = reinterpret_cast<const float4*>(g_attn);
    float4 w0 = c4[t], w1 = c4[t + 256];       // batch loads first (MLP)
    float4 v0 = a4[t], v1 = a4[t + 256];       // L1-hot after first block/SM
    float acc = dot4(w0, v0) + dot4(w1, v1);
    acc = block_sum(acc, sred);
    if (t == 0) g_x[H + r] = acc;
}

// ======== k5: block-per-row. gx = W_ih·x + b_ih ; gh = W_hh·h + b_hh ========
__global__ __launch_bounds__(128) void k5_gru_mats(
        const float* __restrict__ W_ih, const float* __restrict__ W_hh,
        const float* __restrict__ b_ih, const float* __restrict__ b_hh,
        const float* __restrict__ h) {
    __shared__ float sred[4];
    int r = blockIdx.x;              // 0 .. 2*H3-1
    int t = threadIdx.x;             // 128 threads
    float acc = 0.f;
    if (r < H3) {
        // row length HE = 512 float4 -> 4 per thread
        const float4* w4 = reinterpret_cast<const float4*>(W_ih + (size_t)r * HE);
        const float4* x4 = reinterpret_cast<const float4*>(g_x);
        float4 w0 = w4[t], w1 = w4[t + 128], w2 = w4[t + 256], w3 = w4[t + 384];
        acc = dot4(w0, x4[t]) + dot4(w1, x4[t + 128])
            + dot4(w2, x4[t + 256]) + dot4(w3, x4[t + 384]);
        acc = block_sum(acc, sred);
        if (t == 0) g_gx[r] = acc + b_ih[r];
    } else {
        int j = r - H3;
        // row length H = 256 float4 -> 2 per thread
        const float4* w4 = reinterpret_cast<const float4*>(W_hh + (size_t)j * H);
        const float4* h4 = reinterpret_cast<const float4*>(h);
        float4 w0 = w4[t], w1 = w4[t + 128];
        acc = dot4(w0, h4[t]) + dot4(w1, h4[t + 128]);
        acc = block_sum(acc, sred);
        if (t == 0) g_gh[j] = acc + b_hh[j];
    }
}

// ======== k6: gate combine -> h_new ========
__global__ __launch_bounds__(1024) void k6_combine(const float* __restrict__ h,
                                                   float* __restrict__ out_hidden) {
    int i = threadIdx.x;
    float r  = sigmoidf(g_gx[i]         + g_gh[i]);
    float z  = sigmoidf(g_gx[H + i]     + g_gh[H + i]);
    float n  = tanhf   (g_gx[2 * H + i] + r * g_gh[2 * H + i]);
    float hn = (1.0f - z) * n + z * h[i];
    g_hnew[i] = hn;
    out_hidden[i] = hn;
}

// ======== k7: warp-per-row, h_new in registers (L1-hot broadcast loads) ========
__global__ __launch_bounds__(256) void k7_logits(
        const float* __restrict__ W_o, const float* __restrict__ b_o,
        float* __restrict__ logits, int V) {
    int lane = threadIdx.x & 31;
    int v    = (blockIdx.x * blockDim.x + threadIdx.x) >> 5;
    // lane-local slice of h_new: identical addresses across warps -> L1 hits
    const float4* h4 = reinterpret_cast<const float4*>(g_hnew);
    float4 hreg[8];
    #pragma unroll
    for (int k = 0; k < 8; k++) hreg[k] = h4[lane + 32 * k];
    if (v >= V) return;
    const float4* w4 = reinterpret_cast<const float4*>(W_o + (size_t)v * H);
    float4 wv[8];
    #pragma unroll
    for (int k = 0; k < 8; k++) wv[k] = w4[lane + 32 * k];   // 8 LDG.128 batched
    float a0 = 0.f, a1 = 0.f;
    #pragma unroll
    for (int k = 0; k < 8; k += 2) {
        a0 += dot4(wv[k],     hreg[k]);
        a1 += dot4(wv[k + 1], hreg[k + 1]);
    }
    float acc = warp_sum(a0 + a1);
    if (lane == 0) logits[v] = acc + b_o[v];
}

// ======== k8: logsumexp over V (single block) ========
__global__ __launch_bounds__(1024) void k8_lse(const float* __restrict__ logits, int V) {
    __shared__ float red[32];
    __shared__ float bval;
    int t = threadIdx.x;
    float m = -INFINITY;
    for (int v = t; v < V; v += 1024) m = fmaxf(m, logits[v]);
    m = warp_max(m);
    if ((t & 31) == 0) red[t >> 5] = m;
    __syncthreads();
    if (t < 32) { float v = red[t]; v = warp_max(v); if (t == 0) bval = v; }
    __syncthreads();
    float M = bval;
    float s = 0.f;
    for (int v = t; v < V; v += 1024) s += expf(logits[v] - M);
    s = warp_sum(s);
    __syncthreads();
    if ((t & 31) == 0) red[t >> 5] = s;
    __syncthreads();
    if (t < 32) { float v = red[t]; v = warp_sum(v); if (t == 0) g_lse = M + logf(v); }
}

// ======== k9: out[v] = logits[v] - lse (in place) ========
__global__ __launch_bounds__(256) void k9_norm(float* __restrict__ logits, int V) {
    int v = blockIdx.x * blockDim.x + threadIdx.x;
    if (v < V) logits[v] -= g_lse;
}

// ---------------- launch ----------------
extern "C" void kernel_launch(void* const* d_in, const int* in_sizes, int n_in,
                              void* d_out, int out_size) {
    const int*   y_i   = (const int*)  d_in[0];
    const float* h_i   = (const float*)d_in[1];
    const float* cnn_a = (const float*)d_in[2];
    const float* cnn_c = (const float*)d_in[3];
    const float* emb   = (const float*)d_in[4];
    const float* W_t   = (const float*)d_in[5];
    const float* b_t   = (const float*)d_in[6];
    const float* W_ih  = (const float*)d_in[7];
    const float* W_hh  = (const float*)d_in[8];
    const float* b_ih  = (const float*)d_in[9];
    const float* b_hh  = (const float*)d_in[10];
    const float* W_o   = (const float*)d_in[11];
    const float* b_o   = (const float*)d_in[12];

    const int V = in_sizes[11] / H;           // 50257
    float* out        = (float*)d_out;
    float* out_logits = out;                  // first V floats: log_softmax
    float* out_hidden = out + (out_size - H); // last H floats: gru_hidden

    k1_dvec<<<E, 256>>>(y_i, h_i, emb, W_t, b_t);
    dim3 g2(L / 256, ECHUNKS);
    k2_scores<<<g2, 256>>>(cnn_a);
    k3_softmax<<<1, 1024>>>();
    k4_context<<<H, 256>>>(cnn_c);
    k5_gru_mats<<<2 * H3, 128>>>(W_ih, W_hh, b_ih, b_hh, h_i);
    k6_combine<<<1, H>>>(h_i, out_hidden);
    k7_logits<<<(V + 7) / 8, 256>>>(W_o, b_o, out_logits, V);
    k8_lse<<<1, 1024>>>(out_logits, V);
    k9_norm<<<(V + 255) / 256, 256>>>(out_logits, V);
}